// round 6
// baseline (speedup 1.0000x reference)
#include <cuda_runtime.h>
#include <math.h>

// Problem constants
#define Bc   64
#define Tc   512
#define Fc   128
#define Hc   512
#define G4   2048
#define NCTA 128   // persistent CTAs for recurrent kernel (<= 148 SMs, all co-resident)

// ---------------------------------------------------------------------------
// Scratch (device globals; the sanctioned alternative to cudaMalloc)
// ---------------------------------------------------------------------------
__device__ __align__(16) float g_xproj[(size_t)Tc * G4 * Bc];   // [T][2048][64]  256 MB
__device__ __align__(16) float g_hsA[(size_t)Tc * Hc * Bc];     // [T][512][64]    64 MB
__device__ __align__(16) float g_hsB[(size_t)Tc * Hc * Bc];     //                 64 MB
__device__ __align__(16) float g_hT[2 * Hc * Bc];               // h ping-pong [2][512][64]
__device__ __align__(16) float g_h1[64 * Bc];                   // FC hidden [64][64]
__device__ unsigned g_barGen;
__device__ unsigned g_barCount;

// ---------------------------------------------------------------------------
// GEMM: xproj[t][g][b] = sum_k W[g][k] * X_t[k][b] + (bih[g] + bhh[g])
//   mode 0: X is input [B,T,F]  -> X_t[k][b] = X[(b*T + t)*F + k]   (K=128)
//   mode 1: X is hs    [T,H,B]  -> X_t[k][b] = X[((t*H) + k)*B + b] (K=512)
// CTA tile: 128 g x 64 b, 256 threads, 8x4 per thread, K-chunk 16,
// register-prefetch software pipeline.
// ---------------------------------------------------------------------------
__global__ void __launch_bounds__(256)
gemm_xproj(const float* __restrict__ X, const float* __restrict__ W,
           const float* __restrict__ bih, const float* __restrict__ bhh,
           float* __restrict__ out, int K, int mode)
{
    __shared__ float sA[16][132];   // [k][g] padded
    __shared__ float sX[16][68];    // [k][b] padded

    const int tid = threadIdx.x;
    const int t   = blockIdx.y;
    const int g0  = blockIdx.x * 128;
    const int ty  = tid >> 4;       // 0..15 -> g block of 8
    const int tx  = tid & 15;       // 0..15 -> b block of 4

    float acc[8][4];
#pragma unroll
    for (int i = 0; i < 8; ++i)
#pragma unroll
        for (int j = 0; j < 4; ++j) acc[i][j] = 0.f;

    const int nk = K >> 4;

    // register prefetch of chunk 0
    float4 wa[2];
    float4 xa;
    {
#pragma unroll
        for (int it = 0; it < 2; ++it) {
            int idx = tid + it * 256;           // 0..511 float4 units of A tile
            int gl = idx >> 2;
            int kl = (idx & 3) << 2;
            wa[it] = *(const float4*)(W + (size_t)(g0 + gl) * K + kl);
        }
        if (mode == 0) {
            int bl = tid >> 2;
            int kl = (tid & 3) << 2;
            xa = *(const float4*)(X + ((size_t)bl * Tc + t) * Fc + kl);
        } else {
            int kl = tid >> 4;
            int bl = (tid & 15) << 2;
            xa = *(const float4*)(X + ((size_t)t * Hc + kl) * Bc + bl);
        }
    }

    for (int kc = 0; kc < nk; ++kc) {
        __syncthreads();
        // store current prefetch to smem (A transposed to [k][g])
#pragma unroll
        for (int it = 0; it < 2; ++it) {
            int idx = tid + it * 256;
            int gl = idx >> 2;
            int kl = (idx & 3) << 2;
            sA[kl + 0][gl] = wa[it].x;
            sA[kl + 1][gl] = wa[it].y;
            sA[kl + 2][gl] = wa[it].z;
            sA[kl + 3][gl] = wa[it].w;
        }
        if (mode == 0) {
            int bl = tid >> 2;
            int kl = (tid & 3) << 2;
            sX[kl + 0][bl] = xa.x;
            sX[kl + 1][bl] = xa.y;
            sX[kl + 2][bl] = xa.z;
            sX[kl + 3][bl] = xa.w;
        } else {
            int kl = tid >> 4;
            int bl = (tid & 15) << 2;
            *(float4*)&sX[kl][bl] = xa;
        }
        __syncthreads();

        // prefetch next chunk while computing this one
        if (kc + 1 < nk) {
            int k0 = (kc + 1) << 4;
#pragma unroll
            for (int it = 0; it < 2; ++it) {
                int idx = tid + it * 256;
                int gl = idx >> 2;
                int kl = (idx & 3) << 2;
                wa[it] = *(const float4*)(W + (size_t)(g0 + gl) * K + k0 + kl);
            }
            if (mode == 0) {
                int bl = tid >> 2;
                int kl = (tid & 3) << 2;
                xa = *(const float4*)(X + ((size_t)bl * Tc + t) * Fc + k0 + kl);
            } else {
                int kl = tid >> 4;
                int bl = (tid & 15) << 2;
                xa = *(const float4*)(X + ((size_t)t * Hc + k0 + kl) * Bc + bl);
            }
        }

#pragma unroll
        for (int kk = 0; kk < 16; ++kk) {
            float4 a0 = *(const float4*)&sA[kk][ty * 8];
            float4 a1 = *(const float4*)&sA[kk][ty * 8 + 4];
            float4 b0 = *(const float4*)&sX[kk][tx * 4];
            float av[8] = {a0.x, a0.y, a0.z, a0.w, a1.x, a1.y, a1.z, a1.w};
            float bv[4] = {b0.x, b0.y, b0.z, b0.w};
#pragma unroll
            for (int i = 0; i < 8; ++i)
#pragma unroll
                for (int j = 0; j < 4; ++j) acc[i][j] += av[i] * bv[j];
        }
    }

    // epilogue: add folded bias, write [t][g][b]
#pragma unroll
    for (int i = 0; i < 8; ++i) {
        int g = g0 + ty * 8 + i;
        float bias = bih[g] + bhh[g];
        float4 o;
        o.x = acc[i][0] + bias;
        o.y = acc[i][1] + bias;
        o.z = acc[i][2] + bias;
        o.w = acc[i][3] + bias;
        *(float4*)(out + ((size_t)t * G4 + g) * Bc + tx * 4) = o;
    }
}

// ---------------------------------------------------------------------------
// Grid-wide software barrier (all NCTA CTAs resident).
// Sense-reversal via generation counter. __threadfence (fence.gpu) on both
// sides gives release/acquire + L1 invalidate (CCTL.IVALL on sm_103a).
// ---------------------------------------------------------------------------
__device__ __forceinline__ void grid_barrier()
{
    __syncthreads();
    if (threadIdx.x == 0) {
        __threadfence();
        volatile unsigned* vgen = &g_barGen;
        unsigned gen = *vgen;
        unsigned ticket = atomicAdd(&g_barCount, 1u);
        if (ticket == NCTA - 1) {
            g_barCount = 0;
            __threadfence();
            *vgen = gen + 1u;
        } else {
            while (*vgen == gen) { }
            __threadfence();
        }
    }
    __syncthreads();
}

__device__ __forceinline__ float sigmoidf_(float x)
{
    return 1.f / (1.f + __expf(-x));
}

// ---------------------------------------------------------------------------
// Persistent recurrent kernel (one launch per layer).
// 128 CTAs x 256 threads. CTA k owns hidden units u0..u0+3 (gate rows
// {u,512+u,1024+u,1536+u}). W_hh slice (16 rows x 512) in smem k-major as
// sW[k][16] so each thread reads one float4 per k (broadcast, conflict-free).
// h (128 KB) double-buffered in global, staged via double-buffered smem
// chunks with register prefetch (__ldcg = L2-fresh). c lives in smem.
// Thread (b,q): gate type q, units u0+m (m=0..3), batch b.
// ---------------------------------------------------------------------------
__global__ void __launch_bounds__(256, 1)
lstm_rec(const float* __restrict__ xproj, const float* __restrict__ Whh,
         float* __restrict__ hsOut)
{
    extern __shared__ float smem[];
    float* sW = smem;                   // 8192 floats: [k*16 + r]
    float* sH = smem + 8192;            // 2 * 8192 floats: two 128x64 chunks
    float* sG = smem + 8192 + 16384;    // 1024 floats: [gate*256 + m*64 + b]
    float* sC = sG + 1024;              // 256 floats: [m*64 + b]

    const int tid = threadIdx.x;
    const int b   = tid & 63;
    const int q   = tid >> 6;           // gate type: 0=i,1=f,2=g,3=o
    const int u0  = blockIdx.x << 2;    // first owned hidden unit

    // Load W_hh slice once: sW[k*16 + r] = Whh[(r>>2)*512 + u0 + (r&3)][k]
    for (int j = 0; j < 32; ++j) {
        int idx = j * 256 + tid;        // 0..8191
        int r = idx >> 9;               // 0..15
        int k = idx & 511;
        int gate = r >> 2;
        int m = r & 3;
        sW[k * 16 + r] = Whh[(size_t)(gate * Hc + u0 + m) * Hc + k];
    }
    // zero c state and h buffer 0 (t=0 reads buffer 0)
    sC[q * 64 + b] = 0.f;
    g_hT[(u0 + q) * 64 + b] = 0.f;
    __syncthreads();
    grid_barrier();   // all CTAs' zeroed h visible before first step

    const float* wbase = sW + q * 4;
    float4 pre[8];

    for (int t = 0; t < Tc; ++t) {
        const float* xp = xproj + (size_t)t * G4 * Bc;
        float acc[4];
#pragma unroll
        for (int m = 0; m < 4; ++m)
            acc[m] = __ldcs(xp + (size_t)(q * Hc + u0 + m) * Bc + b);

        const float* hin  = g_hT + ((t & 1) ? (Hc * Bc) : 0);
        float*       hout = g_hT + ((t & 1) ? 0 : (Hc * Bc));

        // prefetch chunk 0 (L2-fresh)
#pragma unroll
        for (int j = 0; j < 8; ++j)
            pre[j] = __ldcg((const float4*)hin + j * 256 + tid);

        for (int c = 0; c < 4; ++c) {
            __syncthreads();
            float* sHc = sH + (c & 1) * 8192;
#pragma unroll
            for (int j = 0; j < 8; ++j)
                *((float4*)sHc + j * 256 + tid) = pre[j];
            __syncthreads();
            if (c < 3) {
#pragma unroll
                for (int j = 0; j < 8; ++j)
                    pre[j] = __ldcg((const float4*)hin + (c + 1) * 2048 + j * 256 + tid);
            }
            const float* wc = wbase + (c * 128) * 16;
            const float* hc = sHc + b;
#pragma unroll 8
            for (int kl = 0; kl < 128; ++kl) {
                float  hk = hc[kl * 64];
                float4 w  = *(const float4*)(wc + kl * 16);
                acc[0] += hk * w.x;
                acc[1] += hk * w.y;
                acc[2] += hk * w.z;
                acc[3] += hk * w.w;
            }
        }

        // exchange gates within CTA, then elementwise LSTM update
#pragma unroll
        for (int m = 0; m < 4; ++m)
            sG[q * 256 + m * 64 + b] = acc[m];
        __syncthreads();

        float gi = sigmoidf_(sG[0 * 256 + q * 64 + b]);
        float gf = sigmoidf_(sG[1 * 256 + q * 64 + b]);
        float gg = tanhf(sG[2 * 256 + q * 64 + b]);
        float go = sigmoidf_(sG[3 * 256 + q * 64 + b]);
        float cv = gf * sC[q * 64 + b] + gi * gg;
        sC[q * 64 + b] = cv;
        float hv = go * tanhf(cv);

        hout[(u0 + q) * 64 + b] = hv;
        hsOut[((size_t)t * Hc + u0 + q) * Bc + b] = hv;

        grid_barrier();
    }
}

// ---------------------------------------------------------------------------
// FC head
// ---------------------------------------------------------------------------
__global__ void fc1_kernel(const float* __restrict__ hsLast,
                           const float* __restrict__ W1, const float* __restrict__ b1,
                           float* __restrict__ h1)
{
    int idx = blockIdx.x * 256 + threadIdx.x;   // 0..4095
    int j = idx >> 6;
    int b = idx & 63;
    float v = b1[j];
    for (int h = 0; h < Hc; ++h)
        v += W1[j * Hc + h] * hsLast[h * Bc + b];
    h1[j * 64 + b] = fmaxf(v, 0.f);
}

__global__ void fc2_kernel(const float* __restrict__ h1,
                           const float* __restrict__ W2, const float* __restrict__ b2,
                           float* __restrict__ out)
{
    int b = threadIdx.x;   // 64 threads
    float v = b2[0];
    for (int j = 0; j < 64; ++j)
        v += W2[j] * h1[j * 64 + b];
    out[b] = fmaxf(v, 0.f);
}

// ---------------------------------------------------------------------------
// Launch
// ---------------------------------------------------------------------------
#define REC_SMEM ((8192 + 16384 + 1024 + 256) * 4)   // 103424 bytes

extern "C" void kernel_launch(void* const* d_in, const int* in_sizes, int n_in,
                              void* d_out, int out_size)
{
    const float* x    = (const float*)d_in[0];
    const float* Wih0 = (const float*)d_in[1];
    const float* Whh0 = (const float*)d_in[2];
    const float* bih0 = (const float*)d_in[3];
    const float* bhh0 = (const float*)d_in[4];
    const float* Wih1 = (const float*)d_in[5];
    const float* Whh1 = (const float*)d_in[6];
    const float* bih1 = (const float*)d_in[7];
    const float* bhh1 = (const float*)d_in[8];
    const float* Wih2 = (const float*)d_in[9];
    const float* Whh2 = (const float*)d_in[10];
    const float* bih2 = (const float*)d_in[11];
    const float* bhh2 = (const float*)d_in[12];
    const float* W1   = (const float*)d_in[13];
    const float* b1   = (const float*)d_in[14];
    const float* W2   = (const float*)d_in[15];
    const float* b2   = (const float*)d_in[16];

    float *xproj, *hsA, *hsB, *h1;
    cudaGetSymbolAddress((void**)&xproj, g_xproj);
    cudaGetSymbolAddress((void**)&hsA, g_hsA);
    cudaGetSymbolAddress((void**)&hsB, g_hsB);
    cudaGetSymbolAddress((void**)&h1, g_h1);

    cudaFuncSetAttribute(lstm_rec, cudaFuncAttributeMaxDynamicSharedMemorySize, REC_SMEM);

    dim3 gg(16, Tc);

    // Layer 0
    gemm_xproj<<<gg, 256>>>(x, Wih0, bih0, bhh0, xproj, Fc, 0);
    lstm_rec<<<NCTA, 256, REC_SMEM>>>(xproj, Whh0, hsA);
    // Layer 1
    gemm_xproj<<<gg, 256>>>(hsA, Wih1, bih1, bhh1, xproj, Hc, 1);
    lstm_rec<<<NCTA, 256, REC_SMEM>>>(xproj, Whh1, hsB);
    // Layer 2
    gemm_xproj<<<gg, 256>>>(hsB, Wih2, bih2, bhh2, xproj, Hc, 1);
    lstm_rec<<<NCTA, 256, REC_SMEM>>>(xproj, Whh2, hsA);

    // FC head on last timestep of layer 2
    fc1_kernel<<<16, 256>>>(hsA + (size_t)(Tc - 1) * Hc * Bc, W1, b1, h1);
    fc2_kernel<<<1, 64>>>(h1, W2, b2, (float*)d_out);
}